// round 7
// baseline (speedup 1.0000x reference)
#include <cuda_runtime.h>
#include <cuda_fp16.h>
#include <cstdint>

#define TOKENS 256
#define INF    4096
#define OUTF   11008
#define QZC    (OUTF/8)

#define BM 128
#define BN 64
#define BK 64
#define SPLITK 4
#define KSLICE (INF/SPLITK)   // 1024
#define NT (KSLICE/BK)        // 16
#define NSA 4                 // A-tile cp.async stages

#define LDA 72                // halves; 144B row stride (16B aligned, LDSM conflict-free)
#define LDB 72
#define A_STAGE (BM*LDA*2)    // 18432 B
#define B_STAGE (BN*LDB*2)    // 9216 B
#define SMEM_TOTAL (NSA*A_STAGE + 2*B_STAGE)   // 92160 B

#define N1 (TOKENS*INF/8)     // prep: x split groups
#define N2 (TOKENS*OUTF/4)    // prep: out init float4s

// fp16 copy of x, k-order permuted within each 8-group: [0,4,1,5,2,6,3,7]
// (matches the LOP3 nibble-pair extraction order of packed int4 words)
__device__ __half g_xh[TOKENS * INF];

__global__ void prep_kernel(const float4* __restrict__ x4,
                            const float*  __restrict__ bias,
                            float*        __restrict__ out)
{
    int i = blockIdx.x * blockDim.x + threadIdx.x;
    if (i < N1) {
        float4 a = x4[2 * i], b = x4[2 * i + 1];
        __half2 h0 = __floats2half2_rn(a.x, b.x);
        __half2 h1 = __floats2half2_rn(a.y, b.y);
        __half2 h2 = __floats2half2_rn(a.z, b.z);
        __half2 h3 = __floats2half2_rn(a.w, b.w);
        uint4 o;
        o.x = *(uint32_t*)&h0; o.y = *(uint32_t*)&h1;
        o.z = *(uint32_t*)&h2; o.w = *(uint32_t*)&h3;
        ((uint4*)g_xh)[i] = o;
    } else if (i < N1 + N2) {
        int j = i - N1;
        int c4 = j % (OUTF / 4);
        ((float4*)out)[j] = ((const float4*)bias)[c4];
    }
}

__device__ __forceinline__ void cp16(uint32_t smem, const void* gmem) {
    asm volatile("cp.async.cg.shared.global [%0], [%1], 16;\n" :: "r"(smem), "l"(gmem));
}
__device__ __forceinline__ void cp_commit() {
    asm volatile("cp.async.commit_group;\n" ::: "memory");
}
__device__ __forceinline__ void cp_wait2() {
    asm volatile("cp.async.wait_group 2;\n" ::: "memory");
}
__device__ __forceinline__ uint32_t lop3_ea(uint32_t a, uint32_t b, uint32_t c) {
    uint32_t d;
    asm("lop3.b32 %0, %1, %2, %3, 0xEA;" : "=r"(d) : "r"(a), "r"(b), "r"(c));
    return d;  // (a & b) | c
}
__device__ __forceinline__ void ldsm_x4(uint32_t* r, uint32_t addr) {
    asm volatile("ldmatrix.sync.aligned.m8n8.x4.shared.b16 {%0,%1,%2,%3}, [%4];\n"
                 : "=r"(r[0]), "=r"(r[1]), "=r"(r[2]), "=r"(r[3]) : "r"(addr));
}
__device__ __forceinline__ void mma16816(float* c,
    const uint32_t* a, uint32_t b0, uint32_t b1)
{
    asm volatile(
        "mma.sync.aligned.m16n8k16.row.col.f32.f16.f16.f32 "
        "{%0,%1,%2,%3}, {%4,%5,%6,%7}, {%8,%9}, {%0,%1,%2,%3};\n"
        : "+f"(c[0]), "+f"(c[1]), "+f"(c[2]), "+f"(c[3])
        : "r"(a[0]), "r"(a[1]), "r"(a[2]), "r"(a[3]), "r"(b0), "r"(b1));
}
__device__ __forceinline__ void redg(float* p, float v) {
    asm volatile("red.global.add.f32 [%0], %1;" :: "l"(p), "f"(v) : "memory");
}

extern __shared__ char smem[];

__global__ __launch_bounds__(256, 2)
void gptq_gemm_kernel(const uint32_t* __restrict__ qweight,
                      const uint32_t* __restrict__ qzeros,
                      const float*    __restrict__ scales,
                      float*          __restrict__ out)
{
    const uint32_t sb = (uint32_t)__cvta_generic_to_shared(smem);
    const int tid  = threadIdx.x;
    const int warp = tid >> 5, lane = tid & 31;
    const int m0    = blockIdx.y * BM;
    const int n0    = blockIdx.x * BN;
    const int kbase = blockIdx.z * KSLICE;

    const int wm = warp & 3;     // 4 warps over M (32 rows each)
    const int wn = warp >> 2;    // 2 warps over N (32 cols each)

    // ---- B dequant mapping: 2 packed words / thread / stage ----
    const int n_local = tid & 63;
    const int br0     = tid >> 6;          // word rows br0, br0+4 (of 8 per stage)
    const int n_g     = n0 + n_local;
    const int zsh     = (n_g & 7) * 4;

    // ---- ldmatrix per-lane offsets (within a stage buffer) ----
    const int mi  = lane >> 3;
    const int r_a = (lane & 7) + (mi & 1) * 8;
    const int k_a = (mi >> 1) * 8;
    uint32_t aOff[2];
    #pragma unroll
    for (int i = 0; i < 2; i++)
        aOff[i] = 2u * ((wm * 32 + i * 16 + r_a) * LDA + k_a);

    const int b_row = (lane & 7) + (lane >> 4) * 8;
    const int b_k   = ((lane >> 3) & 1) * 8;
    uint32_t bOff[2];
    #pragma unroll
    for (int jj = 0; jj < 2; jj++)
        bOff[jj] = NSA * A_STAGE + 2u * ((wn * 32 + jj * 16 + b_row) * LDB + b_k);

    float acc[2][4][4];
    #pragma unroll
    for (int i = 0; i < 2; i++)
        #pragma unroll
        for (int j = 0; j < 4; j++)
            #pragma unroll
            for (int r = 0; r < 4; r++) acc[i][j][r] = 0.f;

    uint32_t qw[2][2];
    float ss[2], zz[2];
    const __half2 C1024 = __float2half2_rn(1024.f);

    auto load_q = [&](int fs, int p) {
        const int wr = (kbase >> 3) + fs * 8 + br0;
        qw[p][0] = qweight[(size_t)wr * OUTF + n_g];
        qw[p][1] = qweight[(size_t)(wr + 4) * OUTF + n_g];
        const int g = (kbase + fs * BK) >> 7;
        ss[p] = scales[g * OUTF + n_g];
        zz[p] = (float)(((qzeros[g * QZC + (n_g >> 3)] >> zsh) & 15u) + 1u);
    };

    auto dequant_store = [&](int p) {
        const float s = ss[p];
        __half2 s2  = __float2half2_rn(s);
        __half2 s16 = __float2half2_rn(s * 0.0625f);
        __half2 zc  = __float2half2_rn(-s * zz[p]);
        char* bs = smem + NSA * A_STAGE + p * B_STAGE + (size_t)n_local * (LDB * 2);
        #pragma unroll
        for (int w = 0; w < 2; w++) {
            const uint32_t q  = qw[p][w];
            const uint32_t q8 = q >> 8;
            uint32_t w0 = lop3_ea(q,  0x000f000fu, 0x64006400u);  // {v0,v4}+1024
            uint32_t h1 = lop3_ea(q,  0x00f000f0u, 0x64006400u);  // {16v1,16v5}+1024
            uint32_t w2 = lop3_ea(q8, 0x000f000fu, 0x64006400u);  // {v2,v6}+1024
            uint32_t h3 = lop3_ea(q8, 0x00f000f0u, 0x64006400u);  // {16v3,16v7}+1024
            __half2 p0 = __hfma2(__hsub2(*(__half2*)&w0, C1024), s2,  zc);
            __half2 p1 = __hfma2(__hsub2(*(__half2*)&h1, C1024), s16, zc);
            __half2 p2 = __hfma2(__hsub2(*(__half2*)&w2, C1024), s2,  zc);
            __half2 p3 = __hfma2(__hsub2(*(__half2*)&h3, C1024), s16, zc);
            uint4 v;
            v.x = *(uint32_t*)&p0; v.y = *(uint32_t*)&p1;
            v.z = *(uint32_t*)&p2; v.w = *(uint32_t*)&p3;
            *(uint4*)(bs + (br0 + 4 * w) * 16) = v;
        }
    };

    auto fillA = [&](int fs, int pa) {
        const uint32_t as_ = sb + pa * A_STAGE;
        const __half* src = g_xh + (size_t)m0 * INF + kbase + fs * BK;
        #pragma unroll
        for (int v = 0; v < 4; v++) {
            int idx = tid + v * 256;
            int row = idx >> 3;           // 0..127
            int c   = (idx & 7) * 8;      // k halves
            cp16(as_ + row * (LDA * 2) + c * 2, src + (size_t)row * INF + c);
        }
    };

    // ---- prologue: 3 A stages in flight, B stage 0 stored, qw for 1 loaded ----
    fillA(0, 0); cp_commit();
    fillA(1, 1); cp_commit();
    fillA(2, 2); cp_commit();
    load_q(0, 0);
    dequant_store(0);
    load_q(1, 1);

    // ---- mainloop ----
    #pragma unroll 1
    for (int t = 0; t < NT; t++) {
        const int pa = t & 3, pb = t & 1;
        cp_wait2();
        __syncthreads();                   // A[t] (cp.async) + B[t] (STS) visible

        if (t + 3 < NT) fillA(t + 3, (t + 3) & 3);
        cp_commit();

        const uint32_t aBase = sb + pa * A_STAGE;
        const uint32_t bAdd  = sb + pb * B_STAGE;
        #pragma unroll
        for (int kk = 0; kk < 4; kk++) {
            uint32_t a[2][4], b[2][4];
            #pragma unroll
            for (int i = 0; i < 2; i++)  ldsm_x4(a[i],  aBase + aOff[i]  + kk * 32);
            #pragma unroll
            for (int jj = 0; jj < 2; jj++) ldsm_x4(b[jj], bAdd + bOff[jj] + kk * 32);
            #pragma unroll
            for (int i = 0; i < 2; i++)
                #pragma unroll
                for (int jj = 0; jj < 2; jj++)
                    #pragma unroll
                    for (int h = 0; h < 2; h++)
                        mma16816(acc[i][jj * 2 + h], a[i], b[jj][2 * h], b[jj][2 * h + 1]);
        }

        if (t + 1 < NT) {
            dequant_store((t + 1) & 1);
            if (t + 2 < NT) load_q(t + 2, t & 1);
        }
    }

    // ---- epilogue: RED-accumulate into out (pre-initialized with bias) ----
    const int gId = lane >> 2;
    const int t4  = lane & 3;
    #pragma unroll
    for (int i = 0; i < 2; i++) {
        int mrow = m0 + wm * 32 + i * 16 + gId;
        float* rp = out + (size_t)mrow * OUTF;
        #pragma unroll
        for (int j = 0; j < 4; j++) {
            int ncol = n0 + wn * 32 + j * 8 + t4 * 2;
            redg(rp + ncol,                acc[i][j][0]);
            redg(rp + ncol + 1,            acc[i][j][1]);
            redg(rp + 8 * OUTF + ncol,     acc[i][j][2]);
            redg(rp + 8 * OUTF + ncol + 1, acc[i][j][3]);
        }
    }
}

extern "C" void kernel_launch(void* const* d_in, const int* in_sizes, int n_in,
                              void* d_out, int out_size)
{
    const float*    x       = (const float*)d_in[0];
    const uint32_t* qweight = (const uint32_t*)d_in[1];
    const uint32_t* qzeros  = (const uint32_t*)d_in[2];
    const float*    scales  = (const float*)d_in[3];
    const float*    bias    = (const float*)d_in[4];
    float* out = (float*)d_out;

    static bool attr_done = false;
    if (!attr_done) {
        cudaFuncSetAttribute(gptq_gemm_kernel,
                             cudaFuncAttributeMaxDynamicSharedMemorySize, SMEM_TOTAL);
        attr_done = true;
    }

    prep_kernel<<<(N1 + N2 + 255) / 256, 256>>>((const float4*)x, bias, out);

    dim3 grid(OUTF / BN, TOKENS / BM, SPLITK);   // 172 x 2 x 4 = 1376 CTAs
    gptq_gemm_kernel<<<grid, 256, SMEM_TOTAL>>>(qweight, qzeros, scales, out);
}